// round 13
// baseline (speedup 1.0000x reference)
#include <cuda_runtime.h>
#include <cuda_fp16.h>
#include <cstdint>
#include <math.h>

#define BB 2
#define CC 256
#define HH 256
#define WW 256
#define HWP 65536
#define POOLN 7
#define DIN 12544
#define OUTD 1024
#define NROI 1024
#define KSPLIT 2
#define DINW (DIN / 2)     // 6272 half2 words
#define OUTDW (OUTD / 2)   // 512 half2 words
#define CCW (CC / 2)       // 128 half2 words per pixel

// Scratch (device globals; allocation-free per harness rules)
__device__ uint32_t g_fth[(size_t)BB * HWP * CCW];  // NHWC feat as half2 words (67MB)
__device__ uint32_t g_xh[(size_t)NROI * DINW];      // x half2, word-pair-permuted
__device__ uint32_t g_w1th[(size_t)OUTD * DINW];    // W1^T half2, row-perm + word-perm
__device__ uint32_t g_w2th[(size_t)OUTD * OUTDW];   // W2^T half2, word-perm
__device__ uint32_t g_h1h[(size_t)NROI * OUTDW];    // h1 half2, word-perm
__device__ float    g_part[(size_t)KSPLIT * NROI * OUTD];

// ---------------------------------------------------------------------------
// helpers
// ---------------------------------------------------------------------------
__device__ __forceinline__ uint32_t smem_u32(const void* p) {
    uint32_t a;
    asm("{ .reg .u64 t; cvta.to.shared.u64 t, %1; cvt.u32.u64 %0, t; }"
        : "=r"(a) : "l"(p));
    return a;
}
// pack two floats into half2 word: lo = first element (bits 0-15)
__device__ __forceinline__ uint32_t pack_h2(float lo, float hi) {
    uint32_t r;
    asm("cvt.rn.f16x2.f32 %0, %1, %2;" : "=r"(r) : "f"(hi), "f"(lo));
    return r;
}
__device__ __forceinline__ float2 unpack_h2(uint32_t w) {
    __half2 h = *reinterpret_cast<__half2*>(&w);
    return __half22float2(h);
}
__device__ __forceinline__ void mma_fp16(float c[4], const uint32_t a[4], const uint32_t b[2]) {
    asm volatile(
        "mma.sync.aligned.m16n8k16.row.col.f32.f16.f16.f32 "
        "{%0,%1,%2,%3},{%4,%5,%6,%7},{%8,%9},{%0,%1,%2,%3};"
        : "+f"(c[0]), "+f"(c[1]), "+f"(c[2]), "+f"(c[3])
        : "r"(a[0]), "r"(a[1]), "r"(a[2]), "r"(a[3]), "r"(b[0]), "r"(b[1]));
}
#define CP16(dst, src) \
    asm volatile("cp.async.cg.shared.global [%0], [%1], 16;" :: "r"(dst), "l"(src))
#define CP_COMMIT() asm volatile("cp.async.commit_group;" ::: "memory")
#define CP_WAIT(n)  asm volatile("cp.async.wait_group %0;" :: "n"(n) : "memory")

// word-pair-permutation within 8-word groups: pos = (w&~7)|((w&3)<<1)|((w&7)>>2)
__device__ __forceinline__ int wperm(int w) {
    return (w & ~7) | ((w & 3) << 1) | ((w & 7) >> 2);
}

// ---------------------------------------------------------------------------
// Fused prep: NCHW->NHWC(fp16) transpose + W1^T prep + W2^T prep, one launch.
// Block ranges: [0, 32768) transpose; [32768, 45312) W1; [45312, 46336) W2.
// ---------------------------------------------------------------------------
__global__ void __launch_bounds__(256) prep_all(const float* __restrict__ feat,
                                                const float* __restrict__ W1,
                                                const float* __restrict__ W2) {
    __shared__ float tile[32][33];
    int id = blockIdx.x;
    int tx = threadIdx.x, ty = threadIdx.y;

    if (id < 32768) {
        int b  = id >> 14;
        int p0 = (id & 2047) * 32;
        int c0 = ((id >> 11) & 7) * 32;
        const float* in = feat + (size_t)b * CC * HWP;
        uint32_t* out   = g_fth + (size_t)b * HWP * CCW;
#pragma unroll
        for (int i = 0; i < 32; i += 8)
            tile[ty + i][tx] = in[(size_t)(c0 + ty + i) * HWP + p0 + tx];
        __syncthreads();
        if (tx < 16) {
#pragma unroll
            for (int i = 0; i < 32; i += 8) {
                int row = ty + i;
                uint32_t word = pack_h2(tile[2 * tx][row], tile[2 * tx + 1][row]);
                out[(size_t)(p0 + row) * CCW + (c0 >> 1) + tx] = word;
            }
        }
    } else if (id < 45312) {
        int w = id - 32768;
        int k0 = (w % 392) * 32, n0 = (w / 392) * 32;
#pragma unroll
        for (int i = 0; i < 32; i += 8) {
            int k = k0 + ty + i;
            int prow = (k & 255) * 49 + (k >> 8);
            tile[ty + i][tx] = W1[(size_t)prow * OUTD + n0 + tx];
        }
        __syncthreads();
        if (tx < 16) {
#pragma unroll
            for (int i = 0; i < 32; i += 8) {
                int n = n0 + ty + i;
                uint32_t word = pack_h2(tile[2 * tx][ty + i], tile[2 * tx + 1][ty + i]);
                g_w1th[(size_t)n * DINW + (k0 >> 1) + wperm(tx)] = word;
            }
        }
    } else {
        int w = id - 45312;
        int k0 = (w & 31) * 32, n0 = (w >> 5) * 32;
#pragma unroll
        for (int i = 0; i < 32; i += 8)
            tile[ty + i][tx] = W2[(size_t)(k0 + ty + i) * OUTD + n0 + tx];
        __syncthreads();
        if (tx < 16) {
#pragma unroll
            for (int i = 0; i < 32; i += 8) {
                int n = n0 + ty + i;
                uint32_t word = pack_h2(tile[2 * tx][ty + i], tile[2 * tx + 1][ty + i]);
                g_w2th[(size_t)n * OUTDW + (k0 >> 1) + wperm(tx)] = word;
            }
        }
    }
}

// ---------------------------------------------------------------------------
// Rotated ROI align: 1 ROI/block, 256 threads, fp16 feature map.
// ---------------------------------------------------------------------------
__global__ void __launch_bounds__(256) roi_kernel(const float* __restrict__ proposals) {
    __shared__ int4  soff[196];
    __shared__ float4 swt[196];

    int tid = threadIdx.x;
    int r = blockIdx.x;
    int b = r >> 9;

    const float* pr = proposals + r * 5;
    float cx = pr[0], cy = pr[1], w = pr[2], h = pr[3], th = pr[4];
    float cs = cosf(th), sn = sinf(th);
    float hstep = h / (float)POOLN;
    float wstep = w / (float)POOLN;

    if (tid < 196) {
        int bin = tid >> 2, s = tid & 3;
        int ph = bin / 7, pw = bin % 7;
        int sy = s >> 1, sx = s & 1;
        float yl = -h * 0.5f + hstep * ((float)ph + ((float)sy + 0.5f) * 0.5f);
        float xl = -w * 0.5f + wstep * ((float)pw + ((float)sx + 0.5f) * 0.5f);
        float gx = cx + xl * cs - yl * sn;
        float gy = cy + xl * sn + yl * cs;
        int4 off = make_int4(0, 0, 0, 0);
        float4 wt = make_float4(0.f, 0.f, 0.f, 0.f);
        if (gy > -1.f && gy < (float)HH && gx > -1.f && gx < (float)WW) {
            float y = fminf(fmaxf(gy, 0.f), 255.f);
            float x = fminf(fmaxf(gx, 0.f), 255.f);
            float y0f = floorf(y), x0f = floorf(x);
            int y0 = (int)y0f, x0 = (int)x0f;
            int y1 = min(y0 + 1, 255), x1 = min(x0 + 1, 255);
            float ly = y - y0f, lx = x - x0f;
            float hy = 1.f - ly, hx = 1.f - lx;
            off = make_int4(y0 * 256 + x0, y0 * 256 + x1, y1 * 256 + x0, y1 * 256 + x1);
            wt = make_float4(hy * hx * 0.25f, hy * lx * 0.25f,
                             ly * hx * 0.25f, ly * lx * 0.25f);
        }
        soff[tid] = off;
        swt[tid] = wt;
    }
    __syncthreads();

    int bg = tid >> 5, lt = tid & 31;     // 8 bin-slices x 32 channel-threads
    const uint4* fb = (const uint4*)(g_fth + (size_t)b * HWP * CCW);  // 32 uint4/pixel
    uint32_t* xo = g_xh + (size_t)r * DINW;
    int wp[4];
#pragma unroll
    for (int j = 0; j < 4; j++) wp[j] = wperm(lt * 4 + j);

    for (int bin = bg; bin < 49; bin += 8) {
        float acc[8];
#pragma unroll
        for (int i = 0; i < 8; i++) acc[i] = 0.f;
#pragma unroll
        for (int s = 0; s < 4; ++s) {
            int4 o = soff[bin * 4 + s];
            float4 wv = swt[bin * 4 + s];
            uint4 q00 = fb[(size_t)o.x * 32 + lt];
            uint4 q01 = fb[(size_t)o.y * 32 + lt];
            uint4 q10 = fb[(size_t)o.z * 32 + lt];
            uint4 q11 = fb[(size_t)o.w * 32 + lt];
            const uint32_t* w00 = &q00.x;
            const uint32_t* w01 = &q01.x;
            const uint32_t* w10 = &q10.x;
            const uint32_t* w11 = &q11.x;
#pragma unroll
            for (int j = 0; j < 4; j++) {
                float2 f00 = unpack_h2(w00[j]);
                float2 f01 = unpack_h2(w01[j]);
                float2 f10 = unpack_h2(w10[j]);
                float2 f11 = unpack_h2(w11[j]);
                acc[2 * j]     += wv.x * f00.x + wv.y * f01.x + wv.z * f10.x + wv.w * f11.x;
                acc[2 * j + 1] += wv.x * f00.y + wv.y * f01.y + wv.z * f10.y + wv.w * f11.y;
            }
        }
        uint32_t* base = xo + bin * 128;
#pragma unroll
        for (int j = 0; j < 4; j++)
            base[wp[j]] = pack_h2(acc[2 * j], acc[2 * j + 1]);
    }
}

// ---------------------------------------------------------------------------
// FP16 mma.sync GEMM, BK=64 elem (32 words), 3-stage cp.async pipeline.
// BM=128, BN=128, 512 threads (16 warps 4x4), warp tile 32x32,
// 4 x m16n8k16 k-steps per tile. Smem row stride 40 words.
// Raw fp32 partial output; split-K over blockIdx.z.
// ---------------------------------------------------------------------------
#define SROW 40
#define STG_A_BYTES (128 * SROW * 4)          // 20480
#define STG_BYTES   (256 * SROW * 4)          // 40960
#define NSTG 3
#define SMEM_DYN    (NSTG * STG_BYTES)        // 122880

template <int STAGE>
__global__ void __launch_bounds__(512)
gemm_cp(int klenw, int kstridew) {
    extern __shared__ char dynsmem[];
    const uint32_t* A  = (STAGE == 1) ? g_xh : g_h1h;
    const uint32_t* Bt = (STAGE == 1) ? g_w1th : g_w2th;
    float* C = g_part + (size_t)blockIdx.z * NROI * OUTD;
    const int N = 1024;

    int tid = threadIdx.x;
    int bm = blockIdx.y * 128, bn = blockIdx.x * 128;
    int kbase = blockIdx.z * klenw;

    // loaders: 512 threads; each thread 8 words (2x CP16) for A and for B
    int ra = tid >> 2, qa = tid & 3;
    const uint32_t* agp = A + (size_t)(bm + ra) * kstridew + qa * 8;
    const uint32_t* bgp = Bt + (size_t)(bn + ra) * kstridew + qa * 8;
    uint32_t sbase = smem_u32(dynsmem);
    uint32_t adst = sbase + ra * (SROW * 4) + qa * 32;
    uint32_t bdst = sbase + STG_A_BYTES + ra * (SROW * 4) + qa * 32;

    int warpId = tid >> 5, lane = tid & 31;
    int wm = warpId >> 2;
    int wn = warpId & 3;
    int g = lane >> 2, tig = lane & 3;

    float acc[2][4][4];
#pragma unroll
    for (int mt = 0; mt < 2; mt++)
#pragma unroll
        for (int nt = 0; nt < 4; nt++)
#pragma unroll
            for (int i = 0; i < 4; i++) acc[mt][nt][i] = 0.f;

    const int T = klenw / 32;

#define ISSUE(s, k0w)                                                  \
    {                                                                  \
        uint32_t ao = (s) * STG_BYTES;                                 \
        CP16(adst + ao, agp + (k0w));                                  \
        CP16(adst + ao + 16, agp + (k0w) + 4);                         \
        CP16(bdst + ao, bgp + (k0w));                                  \
        CP16(bdst + ao + 16, bgp + (k0w) + 4);                         \
        CP_COMMIT();                                                   \
    }

    ISSUE(0, kbase);
    ISSUE(1, kbase + 32);

    const uint32_t* smw = (const uint32_t*)dynsmem;

    for (int t = 0; t < T; ++t) {
        CP_WAIT(1);
        __syncthreads();
        if (t + 2 < T) {
            ISSUE((t + 2) % NSTG, kbase + (t + 2) * 32);
        }

        const uint32_t* As_ = smw + ((t % NSTG) * STG_BYTES) / 4;
        const uint32_t* Bs_ = As_ + STG_A_BYTES / 4;

        // 4 k-steps of m16n8k16, fragment-pipelined
        uint2 fa[2][2], fb[4];
        {
            int m0 = wm * 32;
#pragma unroll
            for (int mt = 0; mt < 2; mt++) {
                fa[mt][0] = *(const uint2*)(As_ + (m0 + mt * 16 + g) * SROW + 2 * tig);
                fa[mt][1] = *(const uint2*)(As_ + (m0 + mt * 16 + 8 + g) * SROW + 2 * tig);
            }
#pragma unroll
            for (int nt = 0; nt < 4; nt++)
                fb[nt] = *(const uint2*)(Bs_ + (wn * 32 + nt * 8 + g) * SROW + 2 * tig);
        }
#pragma unroll
        for (int ks = 0; ks < 4; ks++) {
            uint2 na[2][2], nb[4];
            if (ks < 3) {
                int kb = (ks + 1) * 8;
                int m0 = wm * 32;
#pragma unroll
                for (int mt = 0; mt < 2; mt++) {
                    na[mt][0] = *(const uint2*)(As_ + (m0 + mt * 16 + g) * SROW + kb + 2 * tig);
                    na[mt][1] = *(const uint2*)(As_ + (m0 + mt * 16 + 8 + g) * SROW + kb + 2 * tig);
                }
#pragma unroll
                for (int nt = 0; nt < 4; nt++)
                    nb[nt] = *(const uint2*)(Bs_ + (wn * 32 + nt * 8 + g) * SROW + kb + 2 * tig);
            }
#pragma unroll
            for (int mt = 0; mt < 2; mt++) {
                uint32_t afr[4] = {fa[mt][0].x, fa[mt][1].x, fa[mt][0].y, fa[mt][1].y};
#pragma unroll
                for (int nt = 0; nt < 4; nt++) {
                    uint32_t bfr[2] = {fb[nt].x, fb[nt].y};
                    mma_fp16(acc[mt][nt], afr, bfr);
                }
            }
            if (ks < 3) {
#pragma unroll
                for (int mt = 0; mt < 2; mt++) {
                    fa[mt][0] = na[mt][0];
                    fa[mt][1] = na[mt][1];
                }
#pragma unroll
                for (int nt = 0; nt < 4; nt++) fb[nt] = nb[nt];
            }
        }
    }

    // epilogue: raw fp32 partials
#pragma unroll
    for (int mt = 0; mt < 2; mt++) {
        int r0 = bm + wm * 32 + mt * 16 + g;
        int r1 = r0 + 8;
#pragma unroll
        for (int nt = 0; nt < 4; nt++) {
            int cb = bn + wn * 32 + nt * 8 + tig * 2;
            float2 o0, o1;
            o0.x = acc[mt][nt][0]; o0.y = acc[mt][nt][1];
            o1.x = acc[mt][nt][2]; o1.y = acc[mt][nt][3];
            *(float2*)&C[(size_t)r0 * N + cb] = o0;
            *(float2*)&C[(size_t)r1 * N + cb] = o1;
        }
    }
#undef ISSUE
}

// ---------------------------------------------------------------------------
// Combine 1: partials + b1 + relu -> g_h1h (half2 words, word-permuted)
// 4 floats -> one uint2 per thread (1024 blocks; latency-bound kernel).
// Permuted pair (2q, 2q+1) of group G = words (w_q, w_{4+q}) = elements
// (16G+2q, +1) and (16G+8+2q, +1).
// ---------------------------------------------------------------------------
__global__ void combine1(const float* __restrict__ bias) {
    int t = blockIdx.x * 256 + threadIdx.x;
    int G = t >> 2, q = t & 3;
    int base = G * 16 + q * 2;
    const size_t P = (size_t)NROI * OUTD;

    float2 a0 = *(const float2*)&g_part[base];
    float2 a1 = *(const float2*)&g_part[P + base];
    float2 c0 = *(const float2*)&g_part[base + 8];
    float2 c1 = *(const float2*)&g_part[P + base + 8];
    int eb = base & (OUTD - 1);
    float2 ba = *(const float2*)&bias[eb];
    float2 bc = *(const float2*)&bias[eb + 8];

    float a_0 = fmaxf(a0.x + a1.x + ba.x, 0.f);
    float a_1 = fmaxf(a0.y + a1.y + ba.y, 0.f);
    float c_0 = fmaxf(c0.x + c1.x + bc.x, 0.f);
    float c_1 = fmaxf(c0.y + c1.y + bc.y, 0.f);

    uint2 o = make_uint2(pack_h2(a_0, a_1), pack_h2(c_0, c_1));
    *(uint2*)&g_h1h[G * 8 + q * 2] = o;
}

// ---------------------------------------------------------------------------
// Tail: fused combine2 + head. One block per ROI.
// Output layout: boxes [0, 5120), cls [5120, 16384)
// ---------------------------------------------------------------------------
__global__ void __launch_bounds__(256) tail_kernel(
        const float* __restrict__ proposals,
        const float* __restrict__ b2,
        const float* __restrict__ Wcls, const float* __restrict__ bcls,
        const float* __restrict__ Wreg, const float* __restrict__ breg,
        float* __restrict__ out) {
    __shared__ float sh2[OUTD];
    __shared__ float sred[16];
    int r = blockIdx.x;
    int tid = threadIdx.x;
    const size_t P = (size_t)NROI * OUTD;
    size_t rowoff = (size_t)r * OUTD;

    {
        int idx = tid * 4;
        float4 a = *(const float4*)&g_part[rowoff + idx];
        float4 p = *(const float4*)&g_part[P + rowoff + idx];
        float4 bv = *(const float4*)&b2[idx];
        sh2[idx]     = fmaxf(a.x + p.x + bv.x, 0.f);
        sh2[idx + 1] = fmaxf(a.y + p.y + bv.y, 0.f);
        sh2[idx + 2] = fmaxf(a.z + p.z + bv.z, 0.f);
        sh2[idx + 3] = fmaxf(a.w + p.w + bv.w, 0.f);
    }
    __syncthreads();

    int j = tid >> 4, lane = tid & 15;
    float s = 0.f;
    if (j < 11) {
        for (int k = lane; k < OUTD; k += 16) s += sh2[k] * Wcls[k * 11 + j];
    } else {
        int jj = j - 11;
        for (int k = lane; k < OUTD; k += 16) s += sh2[k] * Wreg[k * 5 + jj];
    }
#pragma unroll
    for (int off = 8; off; off >>= 1) s += __shfl_down_sync(0xffffffffu, s, off, 16);
    if (lane == 0) {
        float bb = (j < 11) ? bcls[j] : breg[j - 11];
        sred[j] = s + bb;
    }
    __syncthreads();

    if (tid < 11) out[NROI * 5 + r * 11 + tid] = sred[tid];
    if (tid == 0) {
        const float* pr = proposals + r * 5;
        float p0 = pr[0] * 4.f, p1 = pr[1] * 4.f;
        float p2 = pr[2] * 4.f, p3 = pr[3] * 4.f, p4 = pr[4];
        float r0 = sred[11], r1 = sred[12], r2 = sred[13], r3 = sred[14], r4 = sred[15];
        const float CLV = 4.1351665567423560f;
        const float PI  = 3.14159265358979323846f;
        float bx = p2 * r0 + p0;
        float by = p3 * r1 + p1;
        float bw = p2 * expf(fminf(fmaxf(r2, -CLV), CLV));
        float bh = p3 * expf(fminf(fmaxf(r3, -CLV), CLV));
        float a2 = p4 + r4 + PI * 0.5f;
        float m  = a2 - floorf(a2 / PI) * PI;
        float ba = m - PI * 0.5f;
        float* ob = out + r * 5;
        ob[0] = bx; ob[1] = by; ob[2] = bw; ob[3] = bh; ob[4] = ba;
    }
}

extern "C" void kernel_launch(void* const* d_in, const int* in_sizes, int n_in,
                              void* d_out, int out_size) {
    const float* feat      = (const float*)d_in[0];
    const float* proposals = (const float*)d_in[1];
    const float* W1   = (const float*)d_in[2];
    const float* b1   = (const float*)d_in[3];
    const float* W2   = (const float*)d_in[4];
    const float* b2   = (const float*)d_in[5];
    const float* Wcls = (const float*)d_in[6];
    const float* bcls = (const float*)d_in[7];
    const float* Wreg = (const float*)d_in[8];
    const float* breg = (const float*)d_in[9];
    float* out = (float*)d_out;

    cudaFuncSetAttribute(gemm_cp<1>, cudaFuncAttributeMaxDynamicSharedMemorySize, SMEM_DYN);
    cudaFuncSetAttribute(gemm_cp<2>, cudaFuncAttributeMaxDynamicSharedMemorySize, SMEM_DYN);

    prep_all<<<46336, dim3(32, 8)>>>(feat, W1, W2);
    roi_kernel<<<NROI, 256>>>(proposals);
    gemm_cp<1><<<dim3(8, 8, KSPLIT), 512, SMEM_DYN>>>(DINW / KSPLIT, DINW);
    combine1<<<(NROI * OUTD / 4) / 256, 256>>>(b1);
    gemm_cp<2><<<dim3(8, 8, KSPLIT), 512, SMEM_DYN>>>(OUTDW / KSPLIT, OUTDW);
    tail_kernel<<<NROI, 256>>>(proposals, b2, Wcls, bcls, Wreg, breg, out);
}

// round 14
// speedup vs baseline: 1.0826x; 1.0826x over previous
#include <cuda_runtime.h>
#include <cuda_fp16.h>
#include <cstdint>
#include <math.h>

#define BB 2
#define CC 256
#define HH 256
#define WW 256
#define HWP 65536
#define POOLN 7
#define DIN 12544
#define OUTD 1024
#define NROI 1024
#define KSPLIT 2
#define DINW (DIN / 2)     // 6272 half2 words
#define OUTDW (OUTD / 2)   // 512 half2 words
#define CCW (CC / 2)       // 128 half2 words per pixel

// Scratch (device globals; allocation-free per harness rules)
__device__ uint32_t g_fth[(size_t)BB * HWP * CCW];  // NHWC feat as half2 words (67MB)
__device__ uint32_t g_xh[(size_t)NROI * DINW];      // x half2, word-pair-permuted
__device__ uint32_t g_w1th[(size_t)OUTD * DINW];    // W1^T half2, row-perm + word-perm
__device__ uint32_t g_w2th[(size_t)OUTD * OUTDW];   // W2^T half2, word-perm
__device__ uint32_t g_h1h[(size_t)NROI * OUTDW];    // h1 half2, word-perm
__device__ float    g_part[(size_t)KSPLIT * NROI * OUTD];

// ---------------------------------------------------------------------------
// helpers
// ---------------------------------------------------------------------------
__device__ __forceinline__ uint32_t smem_u32(const void* p) {
    uint32_t a;
    asm("{ .reg .u64 t; cvta.to.shared.u64 t, %1; cvt.u32.u64 %0, t; }"
        : "=r"(a) : "l"(p));
    return a;
}
// pack two floats into half2 word: lo = first element (bits 0-15)
__device__ __forceinline__ uint32_t pack_h2(float lo, float hi) {
    uint32_t r;
    asm("cvt.rn.f16x2.f32 %0, %1, %2;" : "=r"(r) : "f"(hi), "f"(lo));
    return r;
}
__device__ __forceinline__ float2 unpack_h2(uint32_t w) {
    __half2 h = *reinterpret_cast<__half2*>(&w);
    return __half22float2(h);
}
__device__ __forceinline__ void mma_fp16(float c[4], const uint32_t a[4], const uint32_t b[2]) {
    asm volatile(
        "mma.sync.aligned.m16n8k16.row.col.f32.f16.f16.f32 "
        "{%0,%1,%2,%3},{%4,%5,%6,%7},{%8,%9},{%0,%1,%2,%3};"
        : "+f"(c[0]), "+f"(c[1]), "+f"(c[2]), "+f"(c[3])
        : "r"(a[0]), "r"(a[1]), "r"(a[2]), "r"(a[3]), "r"(b[0]), "r"(b[1]));
}
#define CP16(dst, src) \
    asm volatile("cp.async.cg.shared.global [%0], [%1], 16;" :: "r"(dst), "l"(src))
#define CP_COMMIT() asm volatile("cp.async.commit_group;" ::: "memory")
#define CP_WAIT(n)  asm volatile("cp.async.wait_group %0;" :: "n"(n) : "memory")

// word-pair-permutation within 8-word groups: pos = (w&~7)|((w&3)<<1)|((w&7)>>2)
__device__ __forceinline__ int wperm(int w) {
    return (w & ~7) | ((w & 3) << 1) | ((w & 7) >> 2);
}

// ---------------------------------------------------------------------------
// prep_feat: NCHW -> NHWC(fp16) transpose only (roi's dependency).
// ---------------------------------------------------------------------------
__global__ void __launch_bounds__(256) prep_feat(const float* __restrict__ feat) {
    __shared__ float tile[32][33];
    int id = blockIdx.x;
    int tx = threadIdx.x, ty = threadIdx.y;
    int b  = id >> 14;
    int p0 = (id & 2047) * 32;
    int c0 = ((id >> 11) & 7) * 32;
    const float* in = feat + (size_t)b * CC * HWP;
    uint32_t* out   = g_fth + (size_t)b * HWP * CCW;
#pragma unroll
    for (int i = 0; i < 32; i += 8)
        tile[ty + i][tx] = in[(size_t)(c0 + ty + i) * HWP + p0 + tx];
    __syncthreads();
    if (tx < 16) {
#pragma unroll
        for (int i = 0; i < 32; i += 8) {
            int row = ty + i;
            uint32_t word = pack_h2(tile[2 * tx][row], tile[2 * tx + 1][row]);
            out[(size_t)(p0 + row) * CCW + (c0 >> 1) + tx] = word;
        }
    }
}

// ---------------------------------------------------------------------------
// Fused roi + weight-prep launch.
// Blocks [0, 1024): rotated ROI align (1 ROI/block, 256 threads).
// Blocks [1024, 13568+1024): W1^T / W2^T prep (co-scheduled, hides its cost
// behind the gather-bound roi blocks).
// ---------------------------------------------------------------------------
__global__ void __launch_bounds__(256) roi_prepw(const float* __restrict__ proposals,
                                                 const float* __restrict__ W1,
                                                 const float* __restrict__ W2) {
    __shared__ __align__(16) char smbuf[6272];
    int tid = threadIdx.x;

    if (blockIdx.x < 1024) {
        // ---------------- ROI align ----------------
        int4*  soff = (int4*)smbuf;                 // 196 * 16 = 3136 B
        float4* swt = (float4*)(smbuf + 3136);      // 196 * 16 = 3136 B
        int r = blockIdx.x;
        int b = r >> 9;

        const float* pr = proposals + r * 5;
        float cx = pr[0], cy = pr[1], w = pr[2], h = pr[3], th = pr[4];
        float cs = cosf(th), sn = sinf(th);
        float hstep = h / (float)POOLN;
        float wstep = w / (float)POOLN;

        if (tid < 196) {
            int bin = tid >> 2, s = tid & 3;
            int ph = bin / 7, pw = bin % 7;
            int sy = s >> 1, sx = s & 1;
            float yl = -h * 0.5f + hstep * ((float)ph + ((float)sy + 0.5f) * 0.5f);
            float xl = -w * 0.5f + wstep * ((float)pw + ((float)sx + 0.5f) * 0.5f);
            float gx = cx + xl * cs - yl * sn;
            float gy = cy + xl * sn + yl * cs;
            int4 off = make_int4(0, 0, 0, 0);
            float4 wt = make_float4(0.f, 0.f, 0.f, 0.f);
            if (gy > -1.f && gy < (float)HH && gx > -1.f && gx < (float)WW) {
                float y = fminf(fmaxf(gy, 0.f), 255.f);
                float x = fminf(fmaxf(gx, 0.f), 255.f);
                float y0f = floorf(y), x0f = floorf(x);
                int y0 = (int)y0f, x0 = (int)x0f;
                int y1 = min(y0 + 1, 255), x1 = min(x0 + 1, 255);
                float ly = y - y0f, lx = x - x0f;
                float hy = 1.f - ly, hx = 1.f - lx;
                off = make_int4(y0 * 256 + x0, y0 * 256 + x1, y1 * 256 + x0, y1 * 256 + x1);
                wt = make_float4(hy * hx * 0.25f, hy * lx * 0.25f,
                                 ly * hx * 0.25f, ly * lx * 0.25f);
            }
            soff[tid] = off;
            swt[tid] = wt;
        }
        __syncthreads();

        int bg = tid >> 5, lt = tid & 31;     // 8 bin-slices x 32 channel-threads
        const uint4* fb = (const uint4*)(g_fth + (size_t)b * HWP * CCW);
        uint32_t* xo = g_xh + (size_t)r * DINW;
        int wp[4];
#pragma unroll
        for (int j = 0; j < 4; j++) wp[j] = wperm(lt * 4 + j);

        for (int bin = bg; bin < 49; bin += 8) {
            float acc[8];
#pragma unroll
            for (int i = 0; i < 8; i++) acc[i] = 0.f;
#pragma unroll
            for (int s = 0; s < 4; ++s) {
                int4 o = soff[bin * 4 + s];
                float4 wv = swt[bin * 4 + s];
                uint4 q00 = fb[(size_t)o.x * 32 + lt];
                uint4 q01 = fb[(size_t)o.y * 32 + lt];
                uint4 q10 = fb[(size_t)o.z * 32 + lt];
                uint4 q11 = fb[(size_t)o.w * 32 + lt];
                const uint32_t* w00 = &q00.x;
                const uint32_t* w01 = &q01.x;
                const uint32_t* w10 = &q10.x;
                const uint32_t* w11 = &q11.x;
#pragma unroll
                for (int j = 0; j < 4; j++) {
                    float2 f00 = unpack_h2(w00[j]);
                    float2 f01 = unpack_h2(w01[j]);
                    float2 f10 = unpack_h2(w10[j]);
                    float2 f11 = unpack_h2(w11[j]);
                    acc[2 * j]     += wv.x * f00.x + wv.y * f01.x + wv.z * f10.x + wv.w * f11.x;
                    acc[2 * j + 1] += wv.x * f00.y + wv.y * f01.y + wv.z * f10.y + wv.w * f11.y;
                }
            }
            uint32_t* base = xo + bin * 128;
#pragma unroll
            for (int j = 0; j < 4; j++)
                base[wp[j]] = pack_h2(acc[2 * j], acc[2 * j + 1]);
        }
    } else {
        // ---------------- weight prep ----------------
        float (*tile)[33] = (float(*)[33])smbuf;    // 32*33*4 = 4224 B
        int id = blockIdx.x - 1024;
        int tx = tid & 31, ty = tid >> 5;

        if (id < 12544) {
            int k0 = (id % 392) * 32, n0 = (id / 392) * 32;
#pragma unroll
            for (int i = 0; i < 32; i += 8) {
                int k = k0 + ty + i;
                int prow = (k & 255) * 49 + (k >> 8);
                tile[ty + i][tx] = W1[(size_t)prow * OUTD + n0 + tx];
            }
            __syncthreads();
            if (tx < 16) {
#pragma unroll
                for (int i = 0; i < 32; i += 8) {
                    int n = n0 + ty + i;
                    uint32_t word = pack_h2(tile[2 * tx][ty + i], tile[2 * tx + 1][ty + i]);
                    g_w1th[(size_t)n * DINW + (k0 >> 1) + wperm(tx)] = word;
                }
            }
        } else {
            int w = id - 12544;
            int k0 = (w & 31) * 32, n0 = (w >> 5) * 32;
#pragma unroll
            for (int i = 0; i < 32; i += 8)
                tile[ty + i][tx] = W2[(size_t)(k0 + ty + i) * OUTD + n0 + tx];
            __syncthreads();
            if (tx < 16) {
#pragma unroll
                for (int i = 0; i < 32; i += 8) {
                    int n = n0 + ty + i;
                    uint32_t word = pack_h2(tile[2 * tx][ty + i], tile[2 * tx + 1][ty + i]);
                    g_w2th[(size_t)n * OUTDW + (k0 >> 1) + wperm(tx)] = word;
                }
            }
        }
    }
}

// ---------------------------------------------------------------------------
// FP16 mma.sync GEMM, 4-stage cp.async pipeline, raw fp32 partial output.
// BM=128, BN=128, BK=32 elem (16 words), 512 threads (16 warps 4x4),
// warp tile 32x32, 2 x m16n8k16 k-steps per tile. Smem row stride 24 words.
// (R12 configuration — proven fastest.)
// ---------------------------------------------------------------------------
#define SROW 24
#define STG_A_BYTES (128 * SROW * 4)          // 12288
#define STG_BYTES   (256 * SROW * 4)          // 24576
#define NSTG 4
#define SMEM_DYN    (NSTG * STG_BYTES)        // 98304

template <int STAGE>
__global__ void __launch_bounds__(512)
gemm_cp(int klenw, int kstridew) {
    extern __shared__ char dynsmem[];
    const uint32_t* A  = (STAGE == 1) ? g_xh : g_h1h;
    const uint32_t* Bt = (STAGE == 1) ? g_w1th : g_w2th;
    float* C = g_part + (size_t)blockIdx.z * NROI * OUTD;
    const int N = 1024;

    int tid = threadIdx.x;
    int bm = blockIdx.y * 128, bn = blockIdx.x * 128;
    int kbase = blockIdx.z * klenw;

    int ra = tid >> 2, qa = tid & 3;
    const uint32_t* agp = A + (size_t)(bm + ra) * kstridew + qa * 4;
    const uint32_t* bgp = Bt + (size_t)(bn + ra) * kstridew + qa * 4;
    uint32_t sbase = smem_u32(dynsmem);
    uint32_t adst = sbase + ra * (SROW * 4) + qa * 16;
    uint32_t bdst = sbase + STG_A_BYTES + ra * (SROW * 4) + qa * 16;

    int warpId = tid >> 5, lane = tid & 31;
    int wm = warpId >> 2;
    int wn = warpId & 3;
    int g = lane >> 2, tig = lane & 3;

    float acc[2][4][4];
#pragma unroll
    for (int mt = 0; mt < 2; mt++)
#pragma unroll
        for (int nt = 0; nt < 4; nt++)
#pragma unroll
            for (int i = 0; i < 4; i++) acc[mt][nt][i] = 0.f;

    const int T = klenw / 16;

#define ISSUE(s, k0w)                                                  \
    {                                                                  \
        uint32_t ao = (s) * STG_BYTES;                                 \
        CP16(adst + ao, agp + (k0w));                                  \
        CP16(bdst + ao, bgp + (k0w));                                  \
        CP_COMMIT();                                                   \
    }

    ISSUE(0, kbase);
    ISSUE(1, kbase + 16);
    ISSUE(2, kbase + 32);

    const uint32_t* smw = (const uint32_t*)dynsmem;

    for (int t = 0; t < T; ++t) {
        CP_WAIT(2);
        __syncthreads();
        if (t + 3 < T) {
            ISSUE((t + 3) % NSTG, kbase + (t + 3) * 16);
        }

        const uint32_t* As_ = smw + ((t % NSTG) * STG_BYTES) / 4;
        const uint32_t* Bs_ = As_ + STG_A_BYTES / 4;

        uint2 fa[2][2], fb[4];
        {
            int m0 = wm * 32;
#pragma unroll
            for (int mt = 0; mt < 2; mt++) {
                fa[mt][0] = *(const uint2*)(As_ + (m0 + mt * 16 + g) * SROW + 2 * tig);
                fa[mt][1] = *(const uint2*)(As_ + (m0 + mt * 16 + 8 + g) * SROW + 2 * tig);
            }
#pragma unroll
            for (int nt = 0; nt < 4; nt++)
                fb[nt] = *(const uint2*)(Bs_ + (wn * 32 + nt * 8 + g) * SROW + 2 * tig);
        }
#pragma unroll
        for (int ks = 0; ks < 2; ks++) {
            uint2 na[2][2], nb[4];
            if (ks < 1) {
                int kb = 8;
                int m0 = wm * 32;
#pragma unroll
                for (int mt = 0; mt < 2; mt++) {
                    na[mt][0] = *(const uint2*)(As_ + (m0 + mt * 16 + g) * SROW + kb + 2 * tig);
                    na[mt][1] = *(const uint2*)(As_ + (m0 + mt * 16 + 8 + g) * SROW + kb + 2 * tig);
                }
#pragma unroll
                for (int nt = 0; nt < 4; nt++)
                    nb[nt] = *(const uint2*)(Bs_ + (wn * 32 + nt * 8 + g) * SROW + kb + 2 * tig);
            }
#pragma unroll
            for (int mt = 0; mt < 2; mt++) {
                uint32_t afr[4] = {fa[mt][0].x, fa[mt][1].x, fa[mt][0].y, fa[mt][1].y};
#pragma unroll
                for (int nt = 0; nt < 4; nt++) {
                    uint32_t bfr[2] = {fb[nt].x, fb[nt].y};
                    mma_fp16(acc[mt][nt], afr, bfr);
                }
            }
            if (ks < 1) {
#pragma unroll
                for (int mt = 0; mt < 2; mt++) {
                    fa[mt][0] = na[mt][0];
                    fa[mt][1] = na[mt][1];
                }
#pragma unroll
                for (int nt = 0; nt < 4; nt++) fb[nt] = nb[nt];
            }
        }
    }

    // epilogue: raw fp32 partials
#pragma unroll
    for (int mt = 0; mt < 2; mt++) {
        int r0 = bm + wm * 32 + mt * 16 + g;
        int r1 = r0 + 8;
#pragma unroll
        for (int nt = 0; nt < 4; nt++) {
            int cb = bn + wn * 32 + nt * 8 + tig * 2;
            float2 o0, o1;
            o0.x = acc[mt][nt][0]; o0.y = acc[mt][nt][1];
            o1.x = acc[mt][nt][2]; o1.y = acc[mt][nt][3];
            *(float2*)&C[(size_t)r0 * N + cb] = o0;
            *(float2*)&C[(size_t)r1 * N + cb] = o1;
        }
    }
#undef ISSUE
}

// ---------------------------------------------------------------------------
// Combine 1: partials + b1 + relu -> g_h1h (half2 words, word-permuted)
// 8 floats -> one uint4 per thread (R12 configuration).
// ---------------------------------------------------------------------------
__global__ void combine1(const float* __restrict__ bias) {
    int t = blockIdx.x * 256 + threadIdx.x;
    int G = t >> 1, half = t & 1;
    int base = G * 16 + half * 4;
    const size_t P = (size_t)NROI * OUTD;

    float4 a0 = *(const float4*)&g_part[base];
    float4 a1 = *(const float4*)&g_part[P + base];
    float4 c0 = *(const float4*)&g_part[base + 8];
    float4 c1 = *(const float4*)&g_part[P + base + 8];
    int eb = base & (OUTD - 1);
    float4 ba = *(const float4*)&bias[eb];
    float4 bc = *(const float4*)&bias[eb + 8];

    float a_0 = fmaxf(a0.x + a1.x + ba.x, 0.f);
    float a_1 = fmaxf(a0.y + a1.y + ba.y, 0.f);
    float a_2 = fmaxf(a0.z + a1.z + ba.z, 0.f);
    float a_3 = fmaxf(a0.w + a1.w + ba.w, 0.f);
    float c_0 = fmaxf(c0.x + c1.x + bc.x, 0.f);
    float c_1 = fmaxf(c0.y + c1.y + bc.y, 0.f);
    float c_2 = fmaxf(c0.z + c1.z + bc.z, 0.f);
    float c_3 = fmaxf(c0.w + c1.w + bc.w, 0.f);

    uint4 o = make_uint4(pack_h2(a_0, a_1), pack_h2(c_0, c_1),
                         pack_h2(a_2, a_3), pack_h2(c_2, c_3));
    *(uint4*)&g_h1h[G * 8 + half * 4] = o;
}

// ---------------------------------------------------------------------------
// Tail: fused combine2 + head. One block per ROI.
// Output layout: boxes [0, 5120), cls [5120, 16384)
// ---------------------------------------------------------------------------
__global__ void __launch_bounds__(256) tail_kernel(
        const float* __restrict__ proposals,
        const float* __restrict__ b2,
        const float* __restrict__ Wcls, const float* __restrict__ bcls,
        const float* __restrict__ Wreg, const float* __restrict__ breg,
        float* __restrict__ out) {
    __shared__ float sh2[OUTD];
    __shared__ float sred[16];
    int r = blockIdx.x;
    int tid = threadIdx.x;
    const size_t P = (size_t)NROI * OUTD;
    size_t rowoff = (size_t)r * OUTD;

    {
        int idx = tid * 4;
        float4 a = *(const float4*)&g_part[rowoff + idx];
        float4 p = *(const float4*)&g_part[P + rowoff + idx];
        float4 bv = *(const float4*)&b2[idx];
        sh2[idx]     = fmaxf(a.x + p.x + bv.x, 0.f);
        sh2[idx + 1] = fmaxf(a.y + p.y + bv.y, 0.f);
        sh2[idx + 2] = fmaxf(a.z + p.z + bv.z, 0.f);
        sh2[idx + 3] = fmaxf(a.w + p.w + bv.w, 0.f);
    }
    __syncthreads();

    int j = tid >> 4, lane = tid & 15;
    float s = 0.f;
    if (j < 11) {
        for (int k = lane; k < OUTD; k += 16) s += sh2[k] * Wcls[k * 11 + j];
    } else {
        int jj = j - 11;
        for (int k = lane; k < OUTD; k += 16) s += sh2[k] * Wreg[k * 5 + jj];
    }
#pragma unroll
    for (int off = 8; off; off >>= 1) s += __shfl_down_sync(0xffffffffu, s, off, 16);
    if (lane == 0) {
        float bb = (j < 11) ? bcls[j] : breg[j - 11];
        sred[j] = s + bb;
    }
    __syncthreads();

    if (tid < 11) out[NROI * 5 + r * 11 + tid] = sred[tid];
    if (tid == 0) {
        const float* pr = proposals + r * 5;
        float p0 = pr[0] * 4.f, p1 = pr[1] * 4.f;
        float p2 = pr[2] * 4.f, p3 = pr[3] * 4.f, p4 = pr[4];
        float r0 = sred[11], r1 = sred[12], r2 = sred[13], r3 = sred[14], r4 = sred[15];
        const float CLV = 4.1351665567423560f;
        const float PI  = 3.14159265358979323846f;
        float bx = p2 * r0 + p0;
        float by = p3 * r1 + p1;
        float bw = p2 * expf(fminf(fmaxf(r2, -CLV), CLV));
        float bh = p3 * expf(fminf(fmaxf(r3, -CLV), CLV));
        float a2 = p4 + r4 + PI * 0.5f;
        float m  = a2 - floorf(a2 / PI) * PI;
        float ba = m - PI * 0.5f;
        float* ob = out + r * 5;
        ob[0] = bx; ob[1] = by; ob[2] = bw; ob[3] = bh; ob[4] = ba;
    }
}

extern "C" void kernel_launch(void* const* d_in, const int* in_sizes, int n_in,
                              void* d_out, int out_size) {
    const float* feat      = (const float*)d_in[0];
    const float* proposals = (const float*)d_in[1];
    const float* W1   = (const float*)d_in[2];
    const float* b1   = (const float*)d_in[3];
    const float* W2   = (const float*)d_in[4];
    const float* b2   = (const float*)d_in[5];
    const float* Wcls = (const float*)d_in[6];
    const float* bcls = (const float*)d_in[7];
    const float* Wreg = (const float*)d_in[8];
    const float* breg = (const float*)d_in[9];
    float* out = (float*)d_out;

    cudaFuncSetAttribute(gemm_cp<1>, cudaFuncAttributeMaxDynamicSharedMemorySize, SMEM_DYN);
    cudaFuncSetAttribute(gemm_cp<2>, cudaFuncAttributeMaxDynamicSharedMemorySize, SMEM_DYN);

    prep_feat<<<32768, dim3(32, 8)>>>(feat);
    roi_prepw<<<1024 + 13568, 256>>>(proposals, W1, W2);
    gemm_cp<1><<<dim3(8, 8, KSPLIT), 512, SMEM_DYN>>>(DINW / KSPLIT, DINW);
    combine1<<<(NROI * OUTD / 8) / 256, 256>>>(b1);
    gemm_cp<2><<<dim3(8, 8, KSPLIT), 512, SMEM_DYN>>>(OUTDW / KSPLIT, OUTDW);
    tail_kernel<<<NROI, 256>>>(proposals, b2, Wcls, bcls, Wreg, breg, out);
}